// round 11
// baseline (speedup 1.0000x reference)
#include <cuda_runtime.h>
#include <cstdint>

// Bond-percolation flood fill, 8192x8192 periodic lattice.
//   in[0] links : int32 (2,8192,8192) {0,1}   (512 MB)
//   in[1] seed  : int32 (2,)
//   out         : float32 (8192,8192), cluster cells = 1.0f
// p=0.45 < pc=0.5 -> seed cluster is tiny (BFS latency-bound, ~10us).
//
// R9/R10 lesson: SM-store zeroing caps at ~5.9 TB/s regardless of occupancy;
// the driver cudaMemsetAsync path does ~7.3 TB/s. So keep the driver memset
// as the writer and OVERLAP it with the BFS via graph fork-join:
//
//   main stream:  fork-event ---- memset(out, 0, 256MB) ----+--- scatter
//   side stream:        \--- bfs (visited bitmap + queue) --/ (join event)
//
// The BFS writes only its own static scratch (bitmap/queue/count); memset
// writes only `out` -> fully independent, safely parallel. The scatter node
// writes 1.0f to the cluster cells and clears exactly the bits/counters the
// BFS set, so all static state is zero again at the end of every replay
// (deterministic, graph-capturable, allocation-free).

#define GRID_N 8192
#define LOG2_N 13
#define NCELLS (GRID_N * GRID_N)
#define QCAP   (1 << 22)          // 16 MB static queue
#define ONE_F  0x3F800000u        // 1.0f bit pattern
#define NTHR   256

__device__ unsigned int g_visited[NCELLS / 32];  // 8 MB bitmap (zero at start)
__device__ int          d_queue[QCAP];
__device__ int          g_count;
__device__ int          g_ovf;

// --------------------------------------------------------------- BFS -------
__global__ void __launch_bounds__(NTHR, 1)
bfs_kernel(const unsigned int* __restrict__ links,
           const int* __restrict__ seed)
{
    const unsigned int* __restrict__ L0 = links;            // +axis0 bonds
    const unsigned int* __restrict__ L1 = links + NCELLS;   // +axis1 bonds
    const int tid = threadIdx.x;

    __shared__ int s_start, s_end, s_next, s_ovf;

    if (tid == 0) {
        const int a = seed[0] & (GRID_N - 1);
        const int b = seed[1] & (GRID_N - 1);
        const int idx = (a << LOG2_N) | b;
        atomicOr(&g_visited[idx >> 5], 1u << (idx & 31));
        d_queue[0] = idx;
        s_start = 0; s_end = 1; s_next = 1; s_ovf = 0;
    }
    __syncthreads();

    while (true) {
        const int start = s_start;
        const int end   = s_end;
        if (start >= end) break;

        for (int i = start + tid; i < end; i += NTHR) {
            const int idx = d_queue[i];
            const int a = idx >> LOG2_N;
            const int b = idx & (GRID_N - 1);

            // periodic 4-neighborhood:
            //   bond L0[a,b] connects (a,b)<->(a+1,b)
            //   bond L1[a,b] connects (a,b)<->(a,b+1)
            const int nA = (((a + 1) & (GRID_N - 1)) << LOG2_N) | b;
            const int mA = (((a - 1) & (GRID_N - 1)) << LOG2_N) | b;
            const int nB = (a << LOG2_N) | ((b + 1) & (GRID_N - 1));
            const int mB = (a << LOG2_N) | ((b - 1) & (GRID_N - 1));

            const bool o0 = L0[idx] != 0u;
            const bool o1 = L0[mA]  != 0u;
            const bool o2 = L1[idx] != 0u;
            const bool o3 = L1[mB]  != 0u;

            const int  nbr[4] = { nA, mA, nB, mB };
            const bool op [4] = { o0, o1, o2, o3 };

            #pragma unroll
            for (int d = 0; d < 4; d++) {
                if (!op[d]) continue;
                const int m = nbr[d];
                const unsigned int bit = 1u << (m & 31);
                if ((atomicOr(&g_visited[m >> 5], bit) & bit) == 0u) {
                    const int p = atomicAdd(&s_next, 1);
                    if (p < QCAP) d_queue[p] = m;
                    else          s_ovf = 1;        // clamp (never expected)
                }
            }
        }
        __syncthreads();
        if (tid == 0) {
            s_start = s_end;
            s_end   = (s_next < QCAP) ? s_next : QCAP;
        }
        __syncthreads();
    }

    if (tid == 0) {
        g_count = (s_next < QCAP) ? s_next : QCAP;
        g_ovf   = s_ovf;
    }
}

// ------------------------------------------------------------- scatter -----
__global__ void __launch_bounds__(1024, 1)
scatter_kernel(unsigned int* __restrict__ out)
{
    const int tid = threadIdx.x;
    const int n   = g_count;
    const int ovf = g_ovf;

    for (int i = tid; i < n; i += 1024) {
        const int m = d_queue[i];
        out[m] = ONE_F;
    }
    if (!ovf) {
        // clear exactly the bits the BFS set -> bitmap returns to all-zero
        for (int i = tid; i < n; i += 1024)
            atomicAnd(&g_visited[d_queue[i] >> 5], ~(1u << (d_queue[i] & 31)));
    } else {
        // safety path (unreachable for subcritical clusters)
        for (unsigned int i = tid; i < NCELLS / 32; i += 1024)
            g_visited[i] = 0u;
    }
    __syncthreads();
    if (tid == 0) { g_count = 0; g_ovf = 0; }
}

// --------------------------------------------------------------- launch ----
static cudaStream_t g_side    = nullptr;
static cudaEvent_t  g_ev_fork = nullptr;
static cudaEvent_t  g_ev_join = nullptr;

extern "C" void kernel_launch(void* const* d_in, const int* in_sizes, int n_in,
                              void* d_out, int out_size)
{
    const unsigned int* links = (const unsigned int*)d_in[0];
    const int*          seed  = (const int*)d_in[1];
    unsigned int*       out   = (unsigned int*)d_out;
    (void)in_sizes; (void)n_in;

    if (!g_side) {   // host-side resources, created once (no device memory)
        cudaStreamCreateWithFlags(&g_side, cudaStreamNonBlocking);
        cudaEventCreateWithFlags(&g_ev_fork, cudaEventDisableTiming);
        cudaEventCreateWithFlags(&g_ev_join, cudaEventDisableTiming);
    }

    // fork: side stream joins the captured dependency chain
    cudaEventRecord(g_ev_fork, 0);
    cudaStreamWaitEvent(g_side, g_ev_fork, 0);

    // parallel branch A (side): latency-bound BFS into static scratch
    bfs_kernel<<<1, NTHR, 0, g_side>>>(links, seed);
    cudaEventRecord(g_ev_join, g_side);

    // parallel branch B (main): driver memset of the 256 MB output (~7.3 TB/s)
    cudaMemsetAsync(out, 0, (size_t)out_size * sizeof(float), 0);

    // join, then scatter 1.0f into cluster cells + reset scratch
    cudaStreamWaitEvent(0, g_ev_join, 0);
    scatter_kernel<<<1, 1024, 0, 0>>>(out);
}

// round 13
// speedup vs baseline: 1.0901x; 1.0901x over previous
#include <cuda_runtime.h>
#include <cstdint>

// Bond-percolation flood fill, 8192x8192 periodic lattice.
//   in[0] links : int32 (2,8192,8192) {0,1}   (512 MB)
//   in[1] seed  : int32 (2,)
//   out         : float32 (8192,8192), cluster cells = 1.0f
//
// Proven-fastest structure (R8): memset(out) node, then ONE kernel.
// This round speeds the BFS kernel (10.4us -> target ~5us):
//   - frontier queue + visited bitmap live in SHARED memory (1024x1024
//     window around the seed): LDS/ATOMS ~30cyc vs L2 ~250 / ATOMG ~318
//   - warps 4..15 prefetch the links neighborhood (+-128, both planes,
//     center-out) into L2 with ld.global.cg, concurrent with the BFS warps
//   - BFS warps (0..3) sync via named barrier bar.sync 1,128
//   - overflow fallback: R8 global-path BFS (out doubles as visited) --
//     always correct, deterministic for a fixed input.

#define GRID_N 8192
#define LOG2_N 13
#define NCELLS (GRID_N * GRID_N)
#define ONE_F  0x3F800000u
#define NTHR   512
#define BFS_T  128                       // BFS sub-group
#define W      1024                      // smem window width (cells)
#define HALF   512
#define WWORDS (W * W / 32)              // bitmap words (128 KB)
#define SQ_CAP 12288                     // smem queue entries (48 KB)
#define GQ_CAP (1 << 22)                 // fallback global queue
#define DYN_SMEM (WWORDS * 4 + SQ_CAP * 4)

__device__ int d_gqueue[GQ_CAP];         // fallback path only

#define BAR1() asm volatile("bar.sync 1, 128;" ::: "memory")

__global__ void __launch_bounds__(NTHR, 1)
bfs_kernel(const unsigned int* __restrict__ links,
           const int* __restrict__ seed,
           unsigned int* __restrict__ out)
{
    extern __shared__ unsigned int dyn[];
    unsigned int* bmp = dyn;                         // window visited bitmap
    int*          sq  = (int*)(dyn + WWORDS);        // window frontier queue

    __shared__ int s_a0, s_b0, s_start, s_end, s_next, s_ovf;

    const int tid = threadIdx.x;
    const unsigned int* __restrict__ L0 = links;
    const unsigned int* __restrict__ L1 = links + NCELLS;

    // ---- zero window bitmap (all 512 threads; ~0.5us) ----
    {
        uint4* p = (uint4*)bmp;
        const uint4 z = make_uint4(0u, 0u, 0u, 0u);
        for (int i = tid; i < WWORDS / 4; i += NTHR) p[i] = z;
    }
    if (tid == 0) {
        const int a = seed[0] & (GRID_N - 1);
        const int b = seed[1] & (GRID_N - 1);
        s_a0 = a; s_b0 = b;
        sq[0] = (a << LOG2_N) | b;
        s_start = 0; s_end = 1; s_next = 1; s_ovf = 0;
    }
    __syncthreads();
    const int a0 = s_a0, b0 = s_b0;
    if (tid == 0) {
        const int lbit = HALF * W + HALF;            // seed at window center
        bmp[lbit >> 5] |= 1u << (lbit & 31);
    }

    // ================= prefetch warps (threads 128..511) =================
    if (tid >= BFS_T) {
        // pull links rows a0-128..a0+127, cols b0-128..+127, both planes,
        // into L2 (32B sector per load), nearest rows first.
        const int pt = tid - BFS_T;                  // 0..383
        const int base_col = b0 & ~7;                // 32B-aligned col base
        for (int L = pt; L < 256 * 64; L += NTHR - BFS_T) {
            const int k    = L >> 6;                 // row-order 0..255
            const int rest = L & 63;
            const int pl   = rest >> 5;              // plane 0/1
            const int sc   = (rest & 31) - 16;       // sector -16..15
            const int dr   = (k & 1) ? -((k >> 1) + 1) : (k >> 1);
            const int row  = (a0 + dr) & (GRID_N - 1);
            const int col  = (base_col + sc * 8) & (GRID_N - 1);
            const unsigned int* p = links + (size_t)pl * NCELLS
                                  + ((size_t)row << LOG2_N) + col;
            unsigned int v;
            asm volatile("ld.global.cg.u32 %0, [%1];" : "=r"(v) : "l"(p));
            (void)v;
        }
        return;                                      // exit; BFS uses bar 1
    }

    // ================= BFS warps (threads 0..127) =========================
    BAR1();                                          // seed bit visible
    while (true) {
        const int start = s_start;
        const int end   = s_end;
        if (start >= end || s_ovf) break;

        for (int i = start + tid; i < end; i += BFS_T) {
            const int g = sq[i];
            const int a = g >> LOG2_N;
            const int b = g & (GRID_N - 1);

            const int nA = (((a + 1) & (GRID_N - 1)) << LOG2_N) | b;
            const int mA = (((a - 1) & (GRID_N - 1)) << LOG2_N) | b;
            const int nB = (a << LOG2_N) | ((b + 1) & (GRID_N - 1));
            const int mB = (a << LOG2_N) | ((b - 1) & (GRID_N - 1));

            const bool o0 = L0[g]  != 0u;   // (a,b)<->(a+1,b)
            const bool o1 = L0[mA] != 0u;   // (a-1,b)<->(a,b)
            const bool o2 = L1[g]  != 0u;   // (a,b)<->(a,b+1)
            const bool o3 = L1[mB] != 0u;   // (a,b-1)<->(a,b)

            const int  nbr[4] = { nA, mA, nB, mB };
            const bool op [4] = { o0, o1, o2, o3 };

            #pragma unroll
            for (int d = 0; d < 4; d++) {
                if (!op[d]) continue;
                const int m = nbr[d];
                int da = ((m >> LOG2_N) - a0) & (GRID_N - 1);
                if (da >= GRID_N / 2) da -= GRID_N;
                int db = ((m & (GRID_N - 1)) - b0) & (GRID_N - 1);
                if (db >= GRID_N / 2) db -= GRID_N;
                if (da < -HALF || da >= HALF || db < -HALF || db >= HALF) {
                    s_ovf = 1; continue;             // outside window
                }
                const int lbit = (da + HALF) * W + (db + HALF);
                const unsigned int bit = 1u << (lbit & 31);
                if ((atomicOr(&bmp[lbit >> 5], bit) & bit) == 0u) {
                    const int p = atomicAdd(&s_next, 1);
                    if (p < SQ_CAP) sq[p] = m;
                    else            s_ovf = 1;
                }
            }
        }
        BAR1();
        if (tid == 0) {
            s_start = end;
            s_end   = (s_next < SQ_CAP) ? s_next : SQ_CAP;
        }
        BAR1();
    }
    BAR1();

    if (!s_ovf) {
        // ---- fast path: write 1.0f for every cluster cell ----
        const int n = (s_next < SQ_CAP) ? s_next : SQ_CAP;
        for (int i = tid; i < n; i += BFS_T)
            out[sq[i]] = ONE_F;
        return;
    }

    // ================= fallback: global-path BFS (R8, proven) =============
    // `out` (already zeroed by the memset node) doubles as the visited set.
    if (tid == 0) {
        const int g = (a0 << LOG2_N) | b0;
        atomicOr(&out[g], ONE_F);
        d_gqueue[0] = g;
        s_start = 0; s_end = 1; s_next = 1;
    }
    BAR1();
    while (true) {
        const int start = s_start;
        const int end   = s_end;
        if (start >= end) break;

        for (int i = start + tid; i < end; i += BFS_T) {
            const int g = d_gqueue[i];
            const int a = g >> LOG2_N;
            const int b = g & (GRID_N - 1);
            const int nA = (((a + 1) & (GRID_N - 1)) << LOG2_N) | b;
            const int mA = (((a - 1) & (GRID_N - 1)) << LOG2_N) | b;
            const int nB = (a << LOG2_N) | ((b + 1) & (GRID_N - 1));
            const int mB = (a << LOG2_N) | ((b - 1) & (GRID_N - 1));
            const bool o0 = L0[g]  != 0u;
            const bool o1 = L0[mA] != 0u;
            const bool o2 = L1[g]  != 0u;
            const bool o3 = L1[mB] != 0u;
            const int  nbr[4] = { nA, mA, nB, mB };
            const bool op [4] = { o0, o1, o2, o3 };
            #pragma unroll
            for (int d = 0; d < 4; d++) {
                if (!op[d]) continue;
                const int m = nbr[d];
                if ((atomicOr(&out[m], ONE_F) & ONE_F) == 0u) {
                    const int p = atomicAdd(&s_next, 1);
                    if (p < GQ_CAP) d_gqueue[p] = m;
                }
            }
        }
        BAR1();
        if (tid == 0) {
            s_start = s_end;
            s_end   = (s_next < GQ_CAP) ? s_next : GQ_CAP;
        }
        BAR1();
    }
}

// --------------------------------------------------------------- launch ----
extern "C" void kernel_launch(void* const* d_in, const int* in_sizes, int n_in,
                              void* d_out, int out_size)
{
    const unsigned int* links = (const unsigned int*)d_in[0];
    const int*          seed  = (const int*)d_in[1];
    unsigned int*       out   = (unsigned int*)d_out;
    (void)in_sizes; (void)n_in;

    static bool inited = false;          // one-time setup (not a work guard)
    if (!inited) {
        cudaFuncSetAttribute(bfs_kernel,
                             cudaFuncAttributeMaxDynamicSharedMemorySize,
                             DYN_SMEM);
        inited = true;
    }

    // 256 MB zero via the driver path (~7.3 TB/s), then the BFS kernel.
    cudaMemsetAsync(out, 0, (size_t)out_size * sizeof(float));
    bfs_kernel<<<1, NTHR, DYN_SMEM>>>(links, seed, out);
}

// round 14
// speedup vs baseline: 1.1390x; 1.0449x over previous
#include <cuda_runtime.h>
#include <cstdint>

// Bond-percolation flood fill, 8192x8192 periodic lattice.
//   in[0] links : int32 (2,8192,8192) {0,1}   (512 MB)
//   in[1] seed  : int32 (2,)
//   out         : float32 (8192,8192), cluster cells = 1.0f
//
// Structure: memset node zeroes rows [0, 6912) (216 MB @ ~7.3 TB/s), then ONE
// kernel in which:
//   - blocks 1..588 zero rows [6912, 8192) (40 MB @ ~5.9 TB/s, ~6.8us)
//   - block 0 runs the smem-window BFS (~7.1us) CONCURRENTLY
//   - block 0 joins on an intra-kernel counter, then scatters 1.0f
// The 40 MB tail zeroing hides completely under the BFS -> memset shrinks by
// ~5.4us for free. Intra-kernel join is deadlock-free: zero blocks never wait
// on anything, so they always retire and g_done always reaches NZBLK.
// All static state returns to zero each launch -> graph-replay deterministic.

#define GRID_N 8192
#define LOG2_N 13
#define NCELLS (GRID_N * GRID_N)
#define ONE_F  0x3F800000u
#define NTHR   512
#define BFS_T  128                       // BFS sub-group (warps 0..3)
#define W      512                       // smem window width (cells)
#define HALF   256
#define WWORDS (W * W / 32)              // 8192 words = 32 KB bitmap
#define SQ_CAP 4096                      // 16 KB smem queue
#define GQ_CAP (1 << 22)                 // fallback global queue
#define DYN_SMEM (WWORDS * 4 + SQ_CAP * 4)   // 48 KB -> 4 blocks/SM

#define NZBLK  588                       // zero-worker blocks (4/SM x 147)
#define ZROWS  1280                      // rows zeroed by the kernel (40 MB)
#define ZSTART (GRID_N - ZROWS)          // 6912

__device__ int d_gqueue[GQ_CAP];         // fallback path only
__device__ int g_done;                   // zero-block completion counter

#define BAR1() asm volatile("bar.sync 1, 128;" ::: "memory")

__global__ void __launch_bounds__(NTHR, 4)
bfs_kernel(const unsigned int* __restrict__ links,
           const int* __restrict__ seed,
           unsigned int* __restrict__ out)
{
    const int tid = threadIdx.x;

    // ====================== zero blocks (rows 6912..8191) ==================
    if (blockIdx.x != 0) {
        const unsigned int w = blockIdx.x - 1;              // 0..NZBLK-1
        uint4* oz = reinterpret_cast<uint4*>(out + (size_t)ZSTART * GRID_N);
        const unsigned int n16 = (unsigned int)ZROWS * GRID_N / 4; // 2621440
        const uint4 z = make_uint4(0u, 0u, 0u, 0u);
        for (unsigned int i = w * NTHR + tid; i < n16;
             i += (unsigned int)NZBLK * NTHR)
            oz[i] = z;
        __threadfence();                                    // publish stores
        __syncthreads();
        if (tid == 0) atomicAdd(&g_done, 1);                // release
        return;
    }

    // ====================== block 0: BFS ====================================
    extern __shared__ unsigned int dyn[];
    unsigned int* bmp = dyn;                                // window bitmap
    int*          sq  = (int*)(dyn + WWORDS);               // window queue

    __shared__ int s_a0, s_b0, s_start, s_end, s_next, s_ovf;

    const unsigned int* __restrict__ L0 = links;
    const unsigned int* __restrict__ L1 = links + NCELLS;

    // zero window bitmap (all 512 threads, 32 KB -> trivial)
    {
        uint4* p = (uint4*)bmp;
        const uint4 z = make_uint4(0u, 0u, 0u, 0u);
        for (int i = tid; i < WWORDS / 4; i += NTHR) p[i] = z;
    }
    if (tid == 0) {
        const int a = seed[0] & (GRID_N - 1);
        const int b = seed[1] & (GRID_N - 1);
        s_a0 = a; s_b0 = b;
        sq[0] = (a << LOG2_N) | b;
        s_start = 0; s_end = 1; s_next = 1; s_ovf = 0;
        const int lbit = HALF * W + HALF;                   // seed at center
        bmp[lbit >> 5] |= 1u << (lbit & 31);
    }
    __syncthreads();
    const int a0 = s_a0, b0 = s_b0;

    // ---------------- prefetch warps (threads 128..511) --------------------
    if (tid >= BFS_T) {
        // pull links rows a0-128..a0+127 x cols around b0, both planes, into
        // L2 (center-out row order) while the BFS warps run.
        const int pt = tid - BFS_T;                         // 0..383
        const int base_col = b0 & ~7;
        for (int L = pt; L < 256 * 64; L += NTHR - BFS_T) {
            const int k    = L >> 6;
            const int rest = L & 63;
            const int pl   = rest >> 5;
            const int sc   = (rest & 31) - 16;
            const int dr   = (k & 1) ? -((k >> 1) + 1) : (k >> 1);
            const int row  = (a0 + dr) & (GRID_N - 1);
            const int col  = (base_col + sc * 8) & (GRID_N - 1);
            const unsigned int* p = links + (size_t)pl * NCELLS
                                  + ((size_t)row << LOG2_N) + col;
            unsigned int v;
            asm volatile("ld.global.cg.u32 %0, [%1];" : "=r"(v) : "l"(p));
            (void)v;
        }
        return;                                             // BFS uses bar 1
    }

    // ---------------- level-synchronous BFS (threads 0..127) ---------------
    while (true) {
        const int start = s_start;
        const int end   = s_end;
        if (start >= end || s_ovf) break;

        for (int i = start + tid; i < end; i += BFS_T) {
            const int g = sq[i];
            const int a = g >> LOG2_N;
            const int b = g & (GRID_N - 1);

            const int nA = (((a + 1) & (GRID_N - 1)) << LOG2_N) | b;
            const int mA = (((a - 1) & (GRID_N - 1)) << LOG2_N) | b;
            const int nB = (a << LOG2_N) | ((b + 1) & (GRID_N - 1));
            const int mB = (a << LOG2_N) | ((b - 1) & (GRID_N - 1));

            const bool o0 = L0[g]  != 0u;   // (a,b)<->(a+1,b)
            const bool o1 = L0[mA] != 0u;   // (a-1,b)<->(a,b)
            const bool o2 = L1[g]  != 0u;   // (a,b)<->(a,b+1)
            const bool o3 = L1[mB] != 0u;   // (a,b-1)<->(a,b)

            const int  nbr[4] = { nA, mA, nB, mB };
            const bool op [4] = { o0, o1, o2, o3 };

            #pragma unroll
            for (int d = 0; d < 4; d++) {
                if (!op[d]) continue;
                const int m = nbr[d];
                int da = ((m >> LOG2_N) - a0) & (GRID_N - 1);
                if (da >= GRID_N / 2) da -= GRID_N;
                int db = ((m & (GRID_N - 1)) - b0) & (GRID_N - 1);
                if (db >= GRID_N / 2) db -= GRID_N;
                if (da < -HALF || da >= HALF || db < -HALF || db >= HALF) {
                    s_ovf = 1; continue;                    // outside window
                }
                const int lbit = (da + HALF) * W + (db + HALF);
                const unsigned int bit = 1u << (lbit & 31);
                if ((atomicOr(&bmp[lbit >> 5], bit) & bit) == 0u) {
                    const int p = atomicAdd(&s_next, 1);
                    if (p < SQ_CAP) sq[p] = m;
                    else            s_ovf = 1;
                }
            }
        }
        BAR1();
        if (tid == 0) {
            s_start = end;
            s_end   = (s_next < SQ_CAP) ? s_next : SQ_CAP;
        }
        BAR1();
    }
    BAR1();

    // ---------------- join: wait for the 40 MB tail zeroing ----------------
    if (tid == 0) {
        while (atomicAdd(&g_done, 0) < NZBLK) __nanosleep(32);
        g_done = 0;                      // self-reset for the next replay
    }
    BAR1();
    __threadfence();                     // acquire zero-block stores

    if (!s_ovf) {
        // ---- fast path: scatter 1.0f for every cluster cell ----
        const int n = (s_next < SQ_CAP) ? s_next : SQ_CAP;
        for (int i = tid; i < n; i += BFS_T)
            out[sq[i]] = ONE_F;
        return;
    }

    // ---------------- fallback: global-path BFS (proven R8) ----------------
    // `out` is now fully zeroed (memset + tail) -> doubles as visited.
    if (tid == 0) {
        const int g = (a0 << LOG2_N) | b0;
        atomicOr(&out[g], ONE_F);
        d_gqueue[0] = g;
        s_start = 0; s_end = 1; s_next = 1;
    }
    BAR1();
    while (true) {
        const int start = s_start;
        const int end   = s_end;
        if (start >= end) break;

        for (int i = start + tid; i < end; i += BFS_T) {
            const int g = d_gqueue[i];
            const int a = g >> LOG2_N;
            const int b = g & (GRID_N - 1);
            const int nA = (((a + 1) & (GRID_N - 1)) << LOG2_N) | b;
            const int mA = (((a - 1) & (GRID_N - 1)) << LOG2_N) | b;
            const int nB = (a << LOG2_N) | ((b + 1) & (GRID_N - 1));
            const int mB = (a << LOG2_N) | ((b - 1) & (GRID_N - 1));
            const bool o0 = L0[g]  != 0u;
            const bool o1 = L0[mA] != 0u;
            const bool o2 = L1[g]  != 0u;
            const bool o3 = L1[mB] != 0u;
            const int  nbr[4] = { nA, mA, nB, mB };
            const bool op [4] = { o0, o1, o2, o3 };
            #pragma unroll
            for (int d = 0; d < 4; d++) {
                if (!op[d]) continue;
                const int m = nbr[d];
                if ((atomicOr(&out[m], ONE_F) & ONE_F) == 0u) {
                    const int p = atomicAdd(&s_next, 1);
                    if (p < GQ_CAP) d_gqueue[p] = m;
                }
            }
        }
        BAR1();
        if (tid == 0) {
            s_start = s_end;
            s_end   = (s_next < GQ_CAP) ? s_next : GQ_CAP;
        }
        BAR1();
    }
}

// --------------------------------------------------------------- launch ----
extern "C" void kernel_launch(void* const* d_in, const int* in_sizes, int n_in,
                              void* d_out, int out_size)
{
    const unsigned int* links = (const unsigned int*)d_in[0];
    const int*          seed  = (const int*)d_in[1];
    unsigned int*       out   = (unsigned int*)d_out;
    (void)in_sizes; (void)n_in; (void)out_size;

    static bool inited = false;          // one-time setup (not a work guard)
    if (!inited) {
        cudaFuncSetAttribute(bfs_kernel,
                             cudaFuncAttributeMaxDynamicSharedMemorySize,
                             DYN_SMEM);
        inited = true;
    }

    // Zero rows [0, 6912) via the fast driver path (216 MB @ ~7.3 TB/s);
    // the kernel's spare blocks zero the last 1280 rows under the BFS.
    cudaMemsetAsync(out, 0, (size_t)ZSTART * GRID_N * sizeof(float));
    bfs_kernel<<<NZBLK + 1, NTHR, DYN_SMEM>>>(links, seed, out);
}